// round 16
// baseline (speedup 1.0000x reference)
#include <cuda_runtime.h>
#include <math.h>
#include <stdint.h>

#define B_ 16
#define C_ 80
#define N_ 22743
#define K_ 100
#define CELLS_ 7581
#define M_ (C_*K_)
#define CAP_ 2048
#define PADTOT_ 22752
#define GP_ 5688          // 3*(91+361+1444) 4-cell groups per image
#define NSAMP_ 8192
#define NCH_ 16           // class chunks in scan
#define CPC_ 5            // classes per chunk

__device__ float g_boxes[B_*N_*4];
__device__ float g_conf_p[B_*PADTOT_];
__device__ float g_pth[B_*PADTOT_];
__device__ float g_tau[B_];
__device__ int   g_ccnt[B_*C_];
__device__ unsigned long long g_clist[(size_t)B_*C_*CAP_];  // packed (s_bits<<32)|~n
__device__ int   g_fbf[B_*C_];
__device__ float g_top_s[B_*M_];
__device__ float g_top_b[B_*M_*4];
__device__ float g_cand[B_*M_];
__device__ float g_fbq[(size_t)B_*C_*N_];   // fallback scratch (rarely touched)

__constant__ int c_gg[3]   = {361,1444,5776};
__constant__ int c_noff[3] = {0,1083,5415};
__constant__ int c_soff[9] = {0,364,728,1092,2536,3980,5424,11200,16976};

__device__ __forceinline__ float sigmoidf_(float x){ return 1.0f/(1.0f+expf(-x)); }

// ---- stage 1: per-image tau via 8192 exact samples (+ zero counters) --------
__global__ void sample_kernel(const float* __restrict__ f0, const float* __restrict__ f1,
                              const float* __restrict__ f2){
    __shared__ float ss[NSAMP_];
    __shared__ int red[17];
    int b = blockIdx.x, tid = threadIdx.x;
    if (tid < C_){ g_ccnt[b*C_ + tid] = 0; g_fbf[b*C_ + tid] = 0; }
    const float* feats[3] = {f0,f1,f2};
    #pragma unroll
    for (int v = 0; v < NSAMP_/512; v++){
        int j = tid + v*512;
        uint32_t n = ((uint32_t)j*2654435761u + 971u) % N_;
        uint32_t c = ((uint32_t)j*48271u + 17u) % C_;
        int l = (n >= 5415) ? 2 : ((n >= 1083) ? 1 : 0);
        int rel = (int)n - c_noff[l];
        int cell = rel/3, a = rel - cell*3;
        const float* base = feats[l] + ((size_t)(b*255 + a*85))*c_gg[l] + cell;
        float to = base[(size_t)4*c_gg[l]];
        float p  = base[(size_t)(5 + (int)c)*c_gg[l]];
        ss[j] = sigmoidf_(to) * sigmoidf_(p);
    }
    __syncthreads();
    uint32_t lo = 0, hi = 0x3F800000u;
    for (int it = 0; it < 20; it++){
        float mv = __uint_as_float((lo + hi) >> 1);
        int cnt = 0;
        for (int j = tid; j < NSAMP_; j += 512) cnt += (ss[j] >= mv);
        for (int d = 16; d; d >>= 1) cnt += __shfl_down_sync(0xFFFFFFFFu, cnt, d);
        if ((tid & 31) == 0) red[tid >> 5] = cnt;
        __syncthreads();
        if (tid == 0){ int t=0; for (int w=0; w<16; w++) t += red[w]; red[16]=t; }
        __syncthreads();
        if (red[16] >= 144) lo = (lo+hi)>>1; else hi = (lo+hi)>>1;
        __syncthreads();
    }
    if (tid == 0) g_tau[b] = __uint_as_float(lo);
}

// ---- stage 2: decode boxes + conf + pth (fused; needs g_tau) ----------------
__global__ void decode_kernel(const float* __restrict__ f0, const float* __restrict__ f1,
                              const float* __restrict__ f2, const float* __restrict__ anchors,
                              const float* __restrict__ imshape){
    int tid = blockIdx.x*blockDim.x + threadIdx.x;
    if (tid < B_*9){   // init l=0 pad slots of g_pth to +INF
        int b = tid/9, j = tid%9;
        g_pth[(size_t)b*PADTOT_ + (j/3)*364 + 361 + (j%3)] = 1e30f;
    }
    if (tid >= B_*CELLS_) return;
    int b = tid / CELLS_, cp = tid % CELLS_;
    const float* feat; int g,l,coff;
    if (cp < 361)       { feat=f0; g=19; l=0; coff=0;    }
    else if (cp < 1805) { feat=f1; g=38; l=1; coff=361;  }
    else                { feat=f2; g=76; l=2; coff=1805; }
    int cell = cp - coff, gg = g*g;
    int gy = cell/g, gx = cell%g;
    int noff = c_noff[l];

    float imh = imshape[0], imw = imshape[1];
    const float ih = 608.0f, iw = 608.0f;
    float r  = fminf(ih/imh, iw/imw);
    float nh = rintf(imh*r), nw = rintf(imw*r);
    float offy = (ih-nh)*0.5f/ih, offx = (iw-nw)*0.5f/iw;
    float scy = ih/nh, scx = iw/nw;
    float tau = g_tau[b];

    #pragma unroll
    for (int a = 0; a < 3; a++){
        const float* base = feat + ((size_t)b*255 + a*85)*(size_t)gg + cell;
        float tx = base[0], ty = base[(size_t)gg], tw = base[2*(size_t)gg];
        float th = base[3*(size_t)gg], to = base[4*(size_t)gg];
        float conf = sigmoidf_(to);
        float bx = (sigmoidf_(tx) + (float)gx)/(float)g;
        float by = (sigmoidf_(ty) + (float)gy)/(float)g;
        int aidx = (2-l)*3 + a;
        float bw = expf(tw)*anchors[aidx*2+0]/ih;
        float bh = expf(th)*anchors[aidx*2+1]/iw;
        float y = (by-offy)*scy, x = (bx-offx)*scx;
        float hh = bh*scy, ww = bw*scx;
        int n = noff + cell*3 + a;
        float* ob = &g_boxes[((size_t)b*N_ + n)*4];
        ob[0] = (y - hh*0.5f)*imh;
        ob[1] = (x - ww*0.5f)*imw;
        ob[2] = (y + hh*0.5f)*imh;
        ob[3] = (x + ww*0.5f)*imw;
        int sidx = c_soff[l*3+a] + cell;
        g_conf_p[(size_t)b*PADTOT_ + sidx] = conf;
        float v = 1e30f;
        if (conf > tau) v = logf(tau/(conf - tau)) - 3e-3f;
        g_pth[(size_t)b*PADTOT_ + sidx] = v;
    }
}

// ------- big scan: R14 hot path, key emission in rare branches ---------------
__global__ __launch_bounds__(256) void scan_kernel(const float* __restrict__ f0,
                                                   const float* __restrict__ f1,
                                                   const float* __restrict__ f2){
    int gid = blockIdx.x*blockDim.x + threadIdx.x;
    if (gid >= B_*GP_) return;
    int ch = blockIdx.y;
    int b = gid / GP_, r = gid % GP_;
    int l, a, q;
    if (r < 273)       { l = 0; a = r/91;   q = r - a*91;   }
    else if (r < 1356) { int rr=r-273;  l = 1; a = rr/361;  q = rr - a*361;  }
    else               { int rr=r-1356; l = 2; a = rr/1444; q = rr - a*1444; }
    int cell = q*4, gg = c_gg[l], noff = c_noff[l];
    const float* f = (l==0) ? f0 : ((l==1) ? f1 : f2);

    size_t sbase = (size_t)b*PADTOT_ + c_soff[l*3+a] + cell;
    const float* pthp = &g_pth[sbase];
    const float* cfp  = &g_conf_p[sbase];
    const float* base = f + ((size_t)(b*255 + a*85 + 5 + ch*CPC_))*gg + cell;
    int bc0 = b*C_ + ch*CPC_;

    float4 pth;
    float4 P[CPC_];
    if (l == 0){
        bool v1 = cell+1 < gg, v2 = cell+2 < gg, v3 = cell+3 < gg;
        pth.x = pthp[0];
        pth.y = v1 ? pthp[1] : 1e30f;
        pth.z = v2 ? pthp[2] : 1e30f;
        pth.w = v3 ? pthp[3] : 1e30f;
        #pragma unroll
        for (int u = 0; u < CPC_; u++){
            const float* pp = base + (size_t)u*gg;
            P[u].x = pp[0];
            P[u].y = v1 ? pp[1] : -1e30f;
            P[u].z = v2 ? pp[2] : -1e30f;
            P[u].w = v3 ? pp[3] : -1e30f;
        }
    } else {
        pth = *(const float4*)pthp;
        #pragma unroll
        for (int u = 0; u < CPC_; u++)
            P[u] = *(const float4*)(base + (size_t)u*gg);
    }
    float minp = fminf(fminf(pth.x, pth.y), fminf(pth.z, pth.w));
    #pragma unroll
    for (int u = 0; u < CPC_; u++){
        float m = fmaxf(fmaxf(P[u].x, P[u].y), fmaxf(P[u].z, P[u].w));
        if (m >= minp){
            int bc = bc0 + u;
            if (P[u].x >= pth.x){
                int o = atomicAdd(&g_ccnt[bc], 1);
                if (o < CAP_){
                    float s = cfp[0] * sigmoidf_(P[u].x);
                    uint32_t n = (uint32_t)(noff + (cell+0)*3 + a);
                    g_clist[(size_t)bc*CAP_ + o] =
                        (((unsigned long long)__float_as_uint(s)) << 32)
                        | (unsigned long long)(0xFFFFFFFFu - n);
                }
            }
            if (P[u].y >= pth.y){
                int o = atomicAdd(&g_ccnt[bc], 1);
                if (o < CAP_){
                    float s = cfp[1] * sigmoidf_(P[u].y);
                    uint32_t n = (uint32_t)(noff + (cell+1)*3 + a);
                    g_clist[(size_t)bc*CAP_ + o] =
                        (((unsigned long long)__float_as_uint(s)) << 32)
                        | (unsigned long long)(0xFFFFFFFFu - n);
                }
            }
            if (P[u].z >= pth.z){
                int o = atomicAdd(&g_ccnt[bc], 1);
                if (o < CAP_){
                    float s = cfp[2] * sigmoidf_(P[u].z);
                    uint32_t n = (uint32_t)(noff + (cell+2)*3 + a);
                    g_clist[(size_t)bc*CAP_ + o] =
                        (((unsigned long long)__float_as_uint(s)) << 32)
                        | (unsigned long long)(0xFFFFFFFFu - n);
                }
            }
            if (P[u].w >= pth.w){
                int o = atomicAdd(&g_ccnt[bc], 1);
                if (o < CAP_){
                    float s = cfp[3] * sigmoidf_(P[u].w);
                    uint32_t n = (uint32_t)(noff + (cell+3)*3 + a);
                    g_clist[(size_t)bc*CAP_ + o] =
                        (((unsigned long long)__float_as_uint(s)) << 32)
                        | (unsigned long long)(0xFFFFFFFFu - n);
                }
            }
        }
    }
}

// ---- per-(b,c) top-100: coalesced key load + shrink + bitonic-256 -----------
__global__ __launch_bounds__(256) void topc_kernel(){
    __shared__ unsigned long long su[256];
    __shared__ int red2[2];
    __shared__ int s_pos;
    int blk = blockIdx.x, tid = threadIdx.x;
    int b = blk / C_;
    int cnt = g_ccnt[blk];
    if (cnt > CAP_){ if (tid == 0) g_fbf[blk] = 1; return; }
    unsigned long long taukey = ((unsigned long long)__float_as_uint(g_tau[b])) << 32;

    unsigned long long key[8];
    int ge = 0;
    #pragma unroll
    for (int u = 0; u < 8; u++){
        int j = tid + u*256;
        unsigned long long kk = 0ULL;
        if (j < cnt) kk = g_clist[(size_t)blk*CAP_ + j];
        ge += (kk >= taukey);
        key[u] = kk;
    }
    if (tid == 0){ red2[0] = 0; red2[1] = 0; s_pos = 0; }
    __syncthreads();
    for (int d = 16; d; d >>= 1) ge += __shfl_down_sync(0xFFFFFFFFu, ge, d);
    if ((tid & 31) == 0) atomicAdd(&red2[0], ge);
    __syncthreads();
    int cntLo = red2[0];
    __syncthreads();
    if (tid == 0) red2[0] = 0;
    __syncthreads();
    if (cntLo < K_){ if (tid == 0) g_fbf[blk] = 1; return; }

    uint32_t lo = (uint32_t)(taukey >> 32), hi = 0x3F800000u;
    for (int it = 0; it < 24 && cntLo > 256 && hi - lo > 1u; it++){
        uint32_t mid = lo + ((hi - lo) >> 1);
        unsigned long long thr = ((unsigned long long)mid) << 32;
        int buf = it & 1;
        int cc = 0;
        #pragma unroll
        for (int u = 0; u < 8; u++) cc += (key[u] >= thr);
        for (int d = 16; d; d >>= 1) cc += __shfl_down_sync(0xFFFFFFFFu, cc, d);
        if ((tid & 31) == 0) atomicAdd(&red2[buf], cc);
        __syncthreads();
        int total = red2[buf];
        if (tid == 0) red2[buf^1] = 0;
        if (total >= K_){ lo = mid; cntLo = total; } else hi = mid;
        __syncthreads();
    }
    if (cntLo > 256){ if (tid == 0) g_fbf[blk] = 1; return; }

    su[tid] = 0ULL;
    __syncthreads();
    unsigned long long thr = ((unsigned long long)lo) << 32;
    #pragma unroll
    for (int u = 0; u < 8; u++)
        if (key[u] >= thr){ int p = atomicAdd(&s_pos, 1); if (p < 256) su[p] = key[u]; }
    __syncthreads();
    if (s_pos > 256){ if (tid == 0) g_fbf[blk] = 1; return; }

    for (int kk = 2; kk <= 256; kk <<= 1)
        for (int j = kk >> 1; j > 0; j >>= 1){
            int ixj = tid ^ j;
            if (ixj > tid){
                unsigned long long A = su[tid], Bv = su[ixj];
                bool up = ((tid & kk) == 0);
                if (up ? (A < Bv) : (A > Bv)){ su[tid] = Bv; su[ixj] = A; }
            }
            __syncthreads();
        }

    if (tid < K_){
        unsigned long long sv = su[tid];
        int n = (int)(0xFFFFFFFFu - (uint32_t)sv);
        g_top_s[(size_t)blk*K_ + tid] = __uint_as_float((uint32_t)(sv >> 32));
        float* ob = &g_top_b[((size_t)blk*K_ + tid)*4];
        if ((unsigned)n < (unsigned)N_){
            const float* bx = &g_boxes[((size_t)b*N_ + n)*4];
            ob[0]=bx[0]; ob[1]=bx[1]; ob[2]=bx[2]; ob[3]=bx[3];
        } else {
            ob[0]=0.f; ob[1]=0.f; ob[2]=0.f; ob[3]=0.f;
        }
    }
}

// ---- exact fallback for flagged blocks (rare; global scratch) ---------------
__global__ __launch_bounds__(256) void fb_kernel(const float* __restrict__ f0,
                                                 const float* __restrict__ f1,
                                                 const float* __restrict__ f2){
    __shared__ uint32_t bmp[712];
    __shared__ unsigned long long wmax[8];
    int blk = blockIdx.x, tid = threadIdx.x;
    if (!g_fbf[blk]) return;
    int b = blk / C_, c = blk % C_;
    float* q = &g_fbq[(size_t)blk*N_];
    const float* feats[3] = {f0,f1,f2};
    for (int l = 0; l < 3; l++){
        int gg = c_gg[l], noff = c_noff[l];
        for (int a = 0; a < 3; a++){
            const float* pp  = feats[l] + ((size_t)(b*255 + a*85 + 5 + c))*gg;
            const float* cfp = g_conf_p + (size_t)b*PADTOT_ + c_soff[l*3+a];
            for (int i = tid; i < gg; i += 256)
                q[noff + i*3 + a] = cfp[i] * sigmoidf_(pp[i]);
        }
    }
    for (int i = tid; i < 712; i += 256) bmp[i] = 0;
    __syncthreads();
    for (int rr = 0; rr < K_; rr++){
        unsigned long long best = 0ULL;
        for (int i = tid; i < N_; i += 256){
            if (!((bmp[i>>5] >> (i & 31)) & 1u)){
                unsigned long long kk = (((unsigned long long)__float_as_uint(q[i])) << 32)
                                      | (unsigned long long)(0xFFFFFFFFu - (uint32_t)i);
                best = (kk > best) ? kk : best;
            }
        }
        for (int d = 16; d; d >>= 1){
            unsigned long long o = __shfl_down_sync(0xFFFFFFFFu, best, d);
            best = (o > best) ? o : best;
        }
        if ((tid & 31) == 0) wmax[tid >> 5] = best;
        __syncthreads();
        if (tid == 0){
            unsigned long long bb = 0ULL;
            for (int x = 0; x < 8; x++) bb = (wmax[x] > bb) ? wmax[x] : bb;
            int n = (int)(0xFFFFFFFFu - (uint32_t)bb);
            if ((unsigned)n < (unsigned)N_){
                bmp[n>>5] |= (1u << (n & 31));
                g_top_s[(size_t)blk*K_ + rr] = __uint_as_float((uint32_t)(bb >> 32));
                const float* bx = &g_boxes[((size_t)b*N_ + n)*4];
                float* ob = &g_top_b[((size_t)blk*K_ + rr)*4];
                ob[0]=bx[0]; ob[1]=bx[1]; ob[2]=bx[2]; ob[3]=bx[3];
            }
        }
        __syncthreads();
    }
}

// ---------------- greedy NMS per (b,c) — standalone, 128 threads -------------
__global__ void nms_kernel(){
    __shared__ float y1s[K_], x1s[K_], y2s[K_], x2s[K_], ars[K_], scs[K_];
    __shared__ unsigned char vld[K_], sup[K_];
    int blk = blockIdx.x, tid = threadIdx.x;
    if (tid < K_){
        const float* bx = &g_top_b[((size_t)blk*K_ + tid)*4];
        float a0=bx[0], a1=bx[1], a2=bx[2], a3=bx[3];
        y1s[tid]=a0; x1s[tid]=a1; y2s[tid]=a2; x2s[tid]=a3;
        ars[tid] = fmaxf(a2-a0, 0.f)*fmaxf(a3-a1, 0.f);
        float s = g_top_s[(size_t)blk*K_ + tid];
        scs[tid]=s; vld[tid]=(s >= 0.2f); sup[tid]=0;
    }
    __syncthreads();
    for (int i = 0; i < K_; i++){
        bool keep_i = vld[i] && !sup[i];
        if (keep_i && tid > i && tid < K_){
            float iy1=fmaxf(y1s[i],y1s[tid]), ix1=fmaxf(x1s[i],x1s[tid]);
            float iy2=fminf(y2s[i],y2s[tid]), ix2=fminf(x2s[i],x2s[tid]);
            float inter=fmaxf(iy2-iy1,0.f)*fmaxf(ix2-ix1,0.f);
            if (inter/(ars[i]+ars[tid]-inter+1e-9f) > 0.3f) sup[tid]=1;
        }
        __syncthreads();
    }
    if (tid < K_)
        g_cand[(size_t)blk*K_ + tid] = (vld[tid] && !sup[tid]) ? scs[tid] : -1.0f;
}

// ---------------- final per-image top-100 (u64 binary search) ----------------
__global__ __launch_bounds__(512) void final_kernel(float* __restrict__ out){
    __shared__ int red;
    __shared__ unsigned long long list[128];
    __shared__ int pos;
    int b = blockIdx.x, tid = threadIdx.x;
    unsigned long long key[16];
    #pragma unroll
    for (int j = 0; j < 16; j++){
        int i = tid + j*512;
        unsigned long long kk = 0ULL;
        if (i < M_){
            uint32_t u = __float_as_uint(g_cand[(size_t)b*M_ + i]);
            uint32_t m = (u & 0x80000000u) ? ~u : (u | 0x80000000u);
            kk = (((unsigned long long)m) << 32) | (unsigned long long)(0xFFFFFFFFu - (uint32_t)i);
        }
        key[j] = kk;
    }
    unsigned long long lo = 0ULL, hi = 0xFFFFFFFFFFFFFFFFULL;
    for (int it = 0; it < 64 && hi - lo > 1ULL; it++){
        unsigned long long mid = lo + ((hi - lo) >> 1);
        if (tid == 0) red = 0;
        __syncthreads();
        int c = 0;
        #pragma unroll
        for (int j = 0; j < 16; j++) c += (key[j] >= mid);
        for (int d = 16; d; d >>= 1) c += __shfl_down_sync(0xFFFFFFFFu, c, d);
        if ((tid & 31) == 0) atomicAdd(&red, c);
        __syncthreads();
        if (red >= K_) lo = mid; else hi = mid;
        __syncthreads();
    }
    if (tid == 0) pos = 0;
    if (tid < 128) list[tid] = 0ULL;
    __syncthreads();
    #pragma unroll
    for (int j = 0; j < 16; j++)
        if (key[j] >= lo){ int p = atomicAdd(&pos, 1); if (p < 128) list[p] = key[j]; }
    __syncthreads();
    for (int k = 2; k <= 128; k <<= 1)
        for (int j = k >> 1; j > 0; j >>= 1){
            if (tid < 128){
                int ixj = tid ^ j;
                if (ixj > tid){
                    unsigned long long A = list[tid], Bv = list[ixj];
                    bool up = ((tid & k) == 0);
                    if (up ? (A < Bv) : (A > Bv)){ list[tid] = Bv; list[ixj] = A; }
                }
            }
            __syncthreads();
        }
    if (tid < K_){
        unsigned long long sv = list[tid];
        int idx = (int)(0xFFFFFFFFu - (uint32_t)sv);
        uint32_t m = (uint32_t)(sv >> 32);
        uint32_t ub = (m & 0x80000000u) ? (m & 0x7FFFFFFFu) : ~m;
        float* o = out + ((size_t)b*K_ + tid)*6;
        if ((unsigned)idx < (unsigned)M_){
            const float* bx = &g_top_b[((size_t)b*M_ + idx)*4];
            o[0]=bx[0]; o[1]=bx[1]; o[2]=bx[2]; o[3]=bx[3];
            o[4] = __uint_as_float(ub);
            o[5] = (float)(idx / K_);
        } else {
            o[0]=0.f; o[1]=0.f; o[2]=0.f; o[3]=0.f; o[4]=-1.f; o[5]=0.f;
        }
    }
}

extern "C" void kernel_launch(void* const* d_in, const int* in_sizes, int n_in,
                              void* d_out, int out_size){
    const float* f0      = (const float*)d_in[0];
    const float* f1      = (const float*)d_in[1];
    const float* f2      = (const float*)d_in[2];
    const float* anchors = (const float*)d_in[3];
    const float* imshape = (const float*)d_in[4];
    float* out = (float*)d_out;

    sample_kernel<<<B_, 512>>>(f0, f1, f2);
    decode_kernel<<<(B_*CELLS_ + 255)/256, 256>>>(f0, f1, f2, anchors, imshape);
    dim3 sg((B_*GP_ + 255)/256, NCH_);
    scan_kernel<<<sg, 256>>>(f0, f1, f2);
    topc_kernel<<<B_*C_, 256>>>();
    fb_kernel<<<B_*C_, 256>>>(f0, f1, f2);
    nms_kernel<<<B_*C_, 128>>>();
    final_kernel<<<B_, 512>>>(out);
}

// round 17
// speedup vs baseline: 1.0864x; 1.0864x over previous
#include <cuda_runtime.h>
#include <math.h>
#include <stdint.h>

#define B_ 16
#define C_ 80
#define N_ 22743
#define K_ 100
#define CELLS_ 7581
#define M_ (C_*K_)
#define CAP_ 2048
#define PADTOT_ 22752
#define GP_ 5688          // 3*(91+361+1444) 4-cell groups per image
#define NSAMP_ 8192
#define NCH_ 16           // class chunks in scan
#define CPC_ 5            // classes per chunk

__device__ float g_boxes[B_*N_*4];
__device__ float g_conf_p[B_*PADTOT_];
__device__ float g_pth[B_*PADTOT_];
__device__ float g_tau[B_];
__device__ int   g_ccnt[B_*C_];
__device__ int   g_clist[(size_t)B_*C_*CAP_];
__device__ float g_top_s[B_*M_];
__device__ float g_top_b[B_*M_*4];
__device__ float g_cand[B_*M_];
__device__ float g_fbq[(size_t)B_*C_*N_];   // fallback scratch (rarely touched)

__constant__ int c_gg[3]   = {361,1444,5776};
__constant__ int c_noff[3] = {0,1083,5415};
__constant__ int c_soff[9] = {0,364,728,1092,2536,3980,5424,11200,16976};

__device__ __forceinline__ float sigmoidf_(float x){ return 1.0f/(1.0f+expf(-x)); }

// ---- stage 1: per-image tau via 8192 exact samples (+ zero counters) --------
__global__ void sample_kernel(const float* __restrict__ f0, const float* __restrict__ f1,
                              const float* __restrict__ f2){
    __shared__ float ss[NSAMP_];
    __shared__ int red[17];
    int b = blockIdx.x, tid = threadIdx.x;
    if (tid < C_) g_ccnt[b*C_ + tid] = 0;
    const float* feats[3] = {f0,f1,f2};
    #pragma unroll
    for (int v = 0; v < NSAMP_/512; v++){
        int j = tid + v*512;
        uint32_t n = ((uint32_t)j*2654435761u + 971u) % N_;
        uint32_t c = ((uint32_t)j*48271u + 17u) % C_;
        int l = (n >= 5415) ? 2 : ((n >= 1083) ? 1 : 0);
        int rel = (int)n - c_noff[l];
        int cell = rel/3, a = rel - cell*3;
        const float* base = feats[l] + ((size_t)(b*255 + a*85))*c_gg[l] + cell;
        float to = base[(size_t)4*c_gg[l]];
        float p  = base[(size_t)(5 + (int)c)*c_gg[l]];
        ss[j] = sigmoidf_(to) * sigmoidf_(p);
    }
    __syncthreads();
    uint32_t lo = 0, hi = 0x3F800000u;
    for (int it = 0; it < 20; it++){
        float mv = __uint_as_float((lo + hi) >> 1);
        int cnt = 0;
        for (int j = tid; j < NSAMP_; j += 512) cnt += (ss[j] >= mv);
        for (int d = 16; d; d >>= 1) cnt += __shfl_down_sync(0xFFFFFFFFu, cnt, d);
        if ((tid & 31) == 0) red[tid >> 5] = cnt;
        __syncthreads();
        if (tid == 0){ int t=0; for (int w=0; w<16; w++) t += red[w]; red[16]=t; }
        __syncthreads();
        if (red[16] >= 144) lo = (lo+hi)>>1; else hi = (lo+hi)>>1;
        __syncthreads();
    }
    if (tid == 0) g_tau[b] = __uint_as_float(lo);
}

// ---- stage 2: decode boxes + conf + pth (fused; needs g_tau) ----------------
__global__ void decode_kernel(const float* __restrict__ f0, const float* __restrict__ f1,
                              const float* __restrict__ f2, const float* __restrict__ anchors,
                              const float* __restrict__ imshape){
    int tid = blockIdx.x*blockDim.x + threadIdx.x;
    if (tid < B_*9){   // init l=0 pad slots of g_pth to +INF
        int b = tid/9, j = tid%9;
        g_pth[(size_t)b*PADTOT_ + (j/3)*364 + 361 + (j%3)] = 1e30f;
    }
    if (tid >= B_*CELLS_) return;
    int b = tid / CELLS_, cp = tid % CELLS_;
    const float* feat; int g,l,coff;
    if (cp < 361)       { feat=f0; g=19; l=0; coff=0;    }
    else if (cp < 1805) { feat=f1; g=38; l=1; coff=361;  }
    else                { feat=f2; g=76; l=2; coff=1805; }
    int cell = cp - coff, gg = g*g;
    int gy = cell/g, gx = cell%g;
    int noff = c_noff[l];

    float imh = imshape[0], imw = imshape[1];
    const float ih = 608.0f, iw = 608.0f;
    float r  = fminf(ih/imh, iw/imw);
    float nh = rintf(imh*r), nw = rintf(imw*r);
    float offy = (ih-nh)*0.5f/ih, offx = (iw-nw)*0.5f/iw;
    float scy = ih/nh, scx = iw/nw;
    float tau = g_tau[b];

    #pragma unroll
    for (int a = 0; a < 3; a++){
        const float* base = feat + ((size_t)b*255 + a*85)*(size_t)gg + cell;
        float tx = base[0], ty = base[(size_t)gg], tw = base[2*(size_t)gg];
        float th = base[3*(size_t)gg], to = base[4*(size_t)gg];
        float conf = sigmoidf_(to);
        float bx = (sigmoidf_(tx) + (float)gx)/(float)g;
        float by = (sigmoidf_(ty) + (float)gy)/(float)g;
        int aidx = (2-l)*3 + a;
        float bw = expf(tw)*anchors[aidx*2+0]/ih;
        float bh = expf(th)*anchors[aidx*2+1]/iw;
        float y = (by-offy)*scy, x = (bx-offx)*scx;
        float hh = bh*scy, ww = bw*scx;
        int n = noff + cell*3 + a;
        float* ob = &g_boxes[((size_t)b*N_ + n)*4];
        ob[0] = (y - hh*0.5f)*imh;
        ob[1] = (x - ww*0.5f)*imw;
        ob[2] = (y + hh*0.5f)*imh;
        ob[3] = (x + ww*0.5f)*imw;
        int sidx = c_soff[l*3+a] + cell;
        g_conf_p[(size_t)b*PADTOT_ + sidx] = conf;
        float v = 1e30f;
        if (conf > tau) v = logf(tau/(conf - tau)) - 3e-3f;
        g_pth[(size_t)b*PADTOT_ + sidx] = v;
    }
}

// ------- big scan: all loads front-batched (R12/R14 measured config) ---------
__global__ __launch_bounds__(256) void scan_kernel(const float* __restrict__ f0,
                                                   const float* __restrict__ f1,
                                                   const float* __restrict__ f2){
    int gid = blockIdx.x*blockDim.x + threadIdx.x;
    if (gid >= B_*GP_) return;
    int ch = blockIdx.y;
    int b = gid / GP_, r = gid % GP_;
    int l, a, q;
    if (r < 273)       { l = 0; a = r/91;   q = r - a*91;   }
    else if (r < 1356) { int rr=r-273;  l = 1; a = rr/361;  q = rr - a*361;  }
    else               { int rr=r-1356; l = 2; a = rr/1444; q = rr - a*1444; }
    int cell = q*4, gg = c_gg[l], noff = c_noff[l];
    const float* f = (l==0) ? f0 : ((l==1) ? f1 : f2);

    const float* pthp = &g_pth[(size_t)b*PADTOT_ + c_soff[l*3+a] + cell];
    const float* base = f + ((size_t)(b*255 + a*85 + 5 + ch*CPC_))*gg + cell;
    int bc0 = b*C_ + ch*CPC_;

    float4 pth;
    float4 P[CPC_];
    if (l == 0){
        bool v1 = cell+1 < gg, v2 = cell+2 < gg, v3 = cell+3 < gg;
        pth.x = pthp[0];
        pth.y = v1 ? pthp[1] : 1e30f;
        pth.z = v2 ? pthp[2] : 1e30f;
        pth.w = v3 ? pthp[3] : 1e30f;
        #pragma unroll
        for (int u = 0; u < CPC_; u++){
            const float* pp = base + (size_t)u*gg;
            P[u].x = pp[0];
            P[u].y = v1 ? pp[1] : -1e30f;
            P[u].z = v2 ? pp[2] : -1e30f;
            P[u].w = v3 ? pp[3] : -1e30f;
        }
    } else {
        pth = *(const float4*)pthp;
        #pragma unroll
        for (int u = 0; u < CPC_; u++)
            P[u] = *(const float4*)(base + (size_t)u*gg);
    }
    float minp = fminf(fminf(pth.x, pth.y), fminf(pth.z, pth.w));
    #pragma unroll
    for (int u = 0; u < CPC_; u++){
        float m = fmaxf(fmaxf(P[u].x, P[u].y), fmaxf(P[u].z, P[u].w));
        if (m >= minp){
            int bc = bc0 + u;
            if (P[u].x>=pth.x){ int o=atomicAdd(&g_ccnt[bc],1); if(o<CAP_) g_clist[(size_t)bc*CAP_+o]=noff+(cell+0)*3+a; }
            if (P[u].y>=pth.y){ int o=atomicAdd(&g_ccnt[bc],1); if(o<CAP_) g_clist[(size_t)bc*CAP_+o]=noff+(cell+1)*3+a; }
            if (P[u].z>=pth.z){ int o=atomicAdd(&g_ccnt[bc],1); if(o<CAP_) g_clist[(size_t)bc*CAP_+o]=noff+(cell+2)*3+a; }
            if (P[u].w>=pth.w){ int o=atomicAdd(&g_ccnt[bc],1); if(o<CAP_) g_clist[(size_t)bc*CAP_+o]=noff+(cell+3)*3+a; }
        }
    }
}

// ---- select: returns false if this block needs the exact fallback -----------
__device__ bool topc_select(int blk, int b, int c, float tau,
                            const float* __restrict__ f0, const float* __restrict__ f1,
                            const float* __restrict__ f2,
                            unsigned long long* su, int* red2, int* s_pos_p){
    int tid = threadIdx.x;
    int cnt = g_ccnt[blk];
    if (cnt > CAP_) return false;
    const float* feats[3] = {f0,f1,f2};

    unsigned long long key[8];
    int ge = 0;
    #pragma unroll
    for (int u = 0; u < 8; u++){
        int j = tid + u*256;
        unsigned long long kk = 0ULL;
        if (j < cnt){
            int n = g_clist[(size_t)blk*CAP_ + j];
            if ((unsigned)n < (unsigned)N_){
                int l = (n >= 5415) ? 2 : ((n >= 1083) ? 1 : 0);
                int rel = n - c_noff[l];
                int cell = rel/3, a = rel - cell*3;
                float p = feats[l][((size_t)(b*255 + a*85 + 5 + c))*c_gg[l] + cell];
                float conf = g_conf_p[(size_t)b*PADTOT_ + c_soff[l*3+a] + cell];
                float s = conf * sigmoidf_(p);
                ge += (s >= tau);
                kk = (((unsigned long long)__float_as_uint(s)) << 32)
                   | (unsigned long long)(0xFFFFFFFFu - (uint32_t)n);
            }
        }
        key[u] = kk;
    }
    if (tid == 0){ red2[0] = 0; red2[1] = 0; *s_pos_p = 0; }
    __syncthreads();
    for (int d = 16; d; d >>= 1) ge += __shfl_down_sync(0xFFFFFFFFu, ge, d);
    if ((tid & 31) == 0) atomicAdd(&red2[0], ge);
    __syncthreads();
    int cntLo = red2[0];
    __syncthreads();
    if (tid == 0) red2[0] = 0;
    __syncthreads();
    if (cntLo < K_) return false;

    uint32_t lo = __float_as_uint(tau), hi = 0x3F800000u;
    for (int it = 0; it < 24 && cntLo > 256 && hi - lo > 1u; it++){
        uint32_t mid = lo + ((hi - lo) >> 1);
        unsigned long long thr = ((unsigned long long)mid) << 32;
        int buf = it & 1;
        int cc = 0;
        #pragma unroll
        for (int u = 0; u < 8; u++) cc += (key[u] >= thr);
        for (int d = 16; d; d >>= 1) cc += __shfl_down_sync(0xFFFFFFFFu, cc, d);
        if ((tid & 31) == 0) atomicAdd(&red2[buf], cc);
        __syncthreads();
        int total = red2[buf];
        if (tid == 0) red2[buf^1] = 0;
        if (total >= K_){ lo = mid; cntLo = total; } else hi = mid;
        __syncthreads();
    }
    if (cntLo > 256) return false;

    su[tid] = 0ULL;
    __syncthreads();
    unsigned long long thr = ((unsigned long long)lo) << 32;
    #pragma unroll
    for (int u = 0; u < 8; u++)
        if (key[u] >= thr){ int p = atomicAdd(s_pos_p, 1); if (p < 256) su[p] = key[u]; }
    __syncthreads();
    if (*s_pos_p > 256) return false;

    for (int kk = 2; kk <= 256; kk <<= 1)
        for (int j = kk >> 1; j > 0; j >>= 1){
            int ixj = tid ^ j;
            if (ixj > tid){
                unsigned long long A = su[tid], Bv = su[ixj];
                bool up = ((tid & kk) == 0);
                if (up ? (A < Bv) : (A > Bv)){ su[tid] = Bv; su[ixj] = A; }
            }
            __syncthreads();
        }

    if (tid < K_){
        unsigned long long sv = su[tid];
        int n = (int)(0xFFFFFFFFu - (uint32_t)sv);
        g_top_s[(size_t)blk*K_ + tid] = __uint_as_float((uint32_t)(sv >> 32));
        float* ob = &g_top_b[((size_t)blk*K_ + tid)*4];
        if ((unsigned)n < (unsigned)N_){
            const float* bx = &g_boxes[((size_t)b*N_ + n)*4];
            ob[0]=bx[0]; ob[1]=bx[1]; ob[2]=bx[2]; ob[3]=bx[3];
        } else {
            ob[0]=0.f; ob[1]=0.f; ob[2]=0.f; ob[3]=0.f;
        }
    }
    return true;
}

// ---- per-(b,c) top-100 with inline exact fallback ---------------------------
__global__ __launch_bounds__(256) void topc_kernel(const float* __restrict__ f0,
                                                   const float* __restrict__ f1,
                                                   const float* __restrict__ f2){
    __shared__ unsigned long long su[256];
    __shared__ int red2[2];
    __shared__ int s_pos;
    __shared__ uint32_t bmp[712];
    __shared__ unsigned long long wmax[8];
    int blk = blockIdx.x, tid = threadIdx.x;
    int b = blk / C_, c = blk % C_;
    float tau = g_tau[b];

    if (topc_select(blk, b, c, tau, f0, f1, f2, su, red2, &s_pos)) return;

    // ---- exact fallback (block-uniform path; rare) ----
    __syncthreads();
    float* q = &g_fbq[(size_t)blk*N_];
    const float* feats[3] = {f0,f1,f2};
    for (int l = 0; l < 3; l++){
        int gg = c_gg[l], noff = c_noff[l];
        for (int a = 0; a < 3; a++){
            const float* pp  = feats[l] + ((size_t)(b*255 + a*85 + 5 + c))*gg;
            const float* cfp = g_conf_p + (size_t)b*PADTOT_ + c_soff[l*3+a];
            for (int i = tid; i < gg; i += 256)
                q[noff + i*3 + a] = cfp[i] * sigmoidf_(pp[i]);
        }
    }
    for (int i = tid; i < 712; i += 256) bmp[i] = 0;
    __syncthreads();
    for (int rr = 0; rr < K_; rr++){
        unsigned long long best = 0ULL;
        for (int i = tid; i < N_; i += 256){
            if (!((bmp[i>>5] >> (i & 31)) & 1u)){
                unsigned long long kk = (((unsigned long long)__float_as_uint(q[i])) << 32)
                                      | (unsigned long long)(0xFFFFFFFFu - (uint32_t)i);
                best = (kk > best) ? kk : best;
            }
        }
        for (int d = 16; d; d >>= 1){
            unsigned long long o = __shfl_down_sync(0xFFFFFFFFu, best, d);
            best = (o > best) ? o : best;
        }
        if ((tid & 31) == 0) wmax[tid >> 5] = best;
        __syncthreads();
        if (tid == 0){
            unsigned long long bb = 0ULL;
            for (int x = 0; x < 8; x++) bb = (wmax[x] > bb) ? wmax[x] : bb;
            int n = (int)(0xFFFFFFFFu - (uint32_t)bb);
            if ((unsigned)n < (unsigned)N_){
                bmp[n>>5] |= (1u << (n & 31));
                g_top_s[(size_t)blk*K_ + rr] = __uint_as_float((uint32_t)(bb >> 32));
                const float* bx = &g_boxes[((size_t)b*N_ + n)*4];
                float* ob = &g_top_b[((size_t)blk*K_ + rr)*4];
                ob[0]=bx[0]; ob[1]=bx[1]; ob[2]=bx[2]; ob[3]=bx[3];
            }
        }
        __syncthreads();
    }
}

// ---------------- greedy NMS per (b,c) — standalone, 128 threads -------------
__global__ void nms_kernel(){
    __shared__ float y1s[K_], x1s[K_], y2s[K_], x2s[K_], ars[K_], scs[K_];
    __shared__ unsigned char vld[K_], sup[K_];
    int blk = blockIdx.x, tid = threadIdx.x;
    if (tid < K_){
        const float* bx = &g_top_b[((size_t)blk*K_ + tid)*4];
        float a0=bx[0], a1=bx[1], a2=bx[2], a3=bx[3];
        y1s[tid]=a0; x1s[tid]=a1; y2s[tid]=a2; x2s[tid]=a3;
        ars[tid] = fmaxf(a2-a0, 0.f)*fmaxf(a3-a1, 0.f);
        float s = g_top_s[(size_t)blk*K_ + tid];
        scs[tid]=s; vld[tid]=(s >= 0.2f); sup[tid]=0;
    }
    __syncthreads();
    for (int i = 0; i < K_; i++){
        bool keep_i = vld[i] && !sup[i];
        if (keep_i && tid > i && tid < K_){
            float iy1=fmaxf(y1s[i],y1s[tid]), ix1=fmaxf(x1s[i],x1s[tid]);
            float iy2=fminf(y2s[i],y2s[tid]), ix2=fminf(x2s[i],x2s[tid]);
            float inter=fmaxf(iy2-iy1,0.f)*fmaxf(ix2-ix1,0.f);
            if (inter/(ars[i]+ars[tid]-inter+1e-9f) > 0.3f) sup[tid]=1;
        }
        __syncthreads();
    }
    if (tid < K_)
        g_cand[(size_t)blk*K_ + tid] = (vld[tid] && !sup[tid]) ? scs[tid] : -1.0f;
}

// ---------------- final per-image top-100 (u64 binary search) ----------------
__global__ __launch_bounds__(512) void final_kernel(float* __restrict__ out){
    __shared__ int red;
    __shared__ unsigned long long list[128];
    __shared__ int pos;
    int b = blockIdx.x, tid = threadIdx.x;
    unsigned long long key[16];
    #pragma unroll
    for (int j = 0; j < 16; j++){
        int i = tid + j*512;
        unsigned long long kk = 0ULL;
        if (i < M_){
            uint32_t u = __float_as_uint(g_cand[(size_t)b*M_ + i]);
            uint32_t m = (u & 0x80000000u) ? ~u : (u | 0x80000000u);
            kk = (((unsigned long long)m) << 32) | (unsigned long long)(0xFFFFFFFFu - (uint32_t)i);
        }
        key[j] = kk;
    }
    unsigned long long lo = 0ULL, hi = 0xFFFFFFFFFFFFFFFFULL;
    for (int it = 0; it < 64 && hi - lo > 1ULL; it++){
        unsigned long long mid = lo + ((hi - lo) >> 1);
        if (tid == 0) red = 0;
        __syncthreads();
        int c = 0;
        #pragma unroll
        for (int j = 0; j < 16; j++) c += (key[j] >= mid);
        for (int d = 16; d; d >>= 1) c += __shfl_down_sync(0xFFFFFFFFu, c, d);
        if ((tid & 31) == 0) atomicAdd(&red, c);
        __syncthreads();
        if (red >= K_) lo = mid; else hi = mid;
        __syncthreads();
    }
    if (tid == 0) pos = 0;
    if (tid < 128) list[tid] = 0ULL;
    __syncthreads();
    #pragma unroll
    for (int j = 0; j < 16; j++)
        if (key[j] >= lo){ int p = atomicAdd(&pos, 1); if (p < 128) list[p] = key[j]; }
    __syncthreads();
    for (int k = 2; k <= 128; k <<= 1)
        for (int j = k >> 1; j > 0; j >>= 1){
            if (tid < 128){
                int ixj = tid ^ j;
                if (ixj > tid){
                    unsigned long long A = list[tid], Bv = list[ixj];
                    bool up = ((tid & k) == 0);
                    if (up ? (A < Bv) : (A > Bv)){ list[tid] = Bv; list[ixj] = A; }
                }
            }
            __syncthreads();
        }
    if (tid < K_){
        unsigned long long sv = list[tid];
        int idx = (int)(0xFFFFFFFFu - (uint32_t)sv);
        uint32_t m = (uint32_t)(sv >> 32);
        uint32_t ub = (m & 0x80000000u) ? (m & 0x7FFFFFFFu) : ~m;
        float* o = out + ((size_t)b*K_ + tid)*6;
        if ((unsigned)idx < (unsigned)M_){
            const float* bx = &g_top_b[((size_t)b*M_ + idx)*4];
            o[0]=bx[0]; o[1]=bx[1]; o[2]=bx[2]; o[3]=bx[3];
            o[4] = __uint_as_float(ub);
            o[5] = (float)(idx / K_);
        } else {
            o[0]=0.f; o[1]=0.f; o[2]=0.f; o[3]=0.f; o[4]=-1.f; o[5]=0.f;
        }
    }
}

extern "C" void kernel_launch(void* const* d_in, const int* in_sizes, int n_in,
                              void* d_out, int out_size){
    const float* f0      = (const float*)d_in[0];
    const float* f1      = (const float*)d_in[1];
    const float* f2      = (const float*)d_in[2];
    const float* anchors = (const float*)d_in[3];
    const float* imshape = (const float*)d_in[4];
    float* out = (float*)d_out;

    sample_kernel<<<B_, 512>>>(f0, f1, f2);
    decode_kernel<<<(B_*CELLS_ + 255)/256, 256>>>(f0, f1, f2, anchors, imshape);
    dim3 sg((B_*GP_ + 255)/256, NCH_);
    scan_kernel<<<sg, 256>>>(f0, f1, f2);
    topc_kernel<<<B_*C_, 256>>>(f0, f1, f2);
    nms_kernel<<<B_*C_, 128>>>();
    final_kernel<<<B_, 512>>>(out);
}